// round 17
// baseline (speedup 1.0000x reference)
#include <cuda_runtime.h>
#include <math.h>

// Problem dims (fixed by setup_inputs)
constexpr int B = 8, H = 384, W = 768;
constexpr int HW = H * W;              // 294912
constexpr int NPIX = B * HW;           // 2359296

// Accumulators: 0 photo_fw, 1 photo_bw, 2 census_fw, 3 census_bw, 4 mask_fw_sum, 5 mask_bw_sum
// Zero-initialized at module load; the last census block re-zeroes after reading.
__device__ double g_acc[6];
__device__ unsigned int g_ctr;   // census block completion counter (zero-init)

// Scratch gray maps (intensity*255) and backward mask
__device__ float g_g1[NPIX];    // gray(img1)*255
__device__ float g_g2[NPIX];    // gray(img2)*255
__device__ float g_g1w[NPIX];   // gray(warp(img1, flow_bw))*255
__device__ float g_g2w[NPIX];   // gray(warp(img2, flow_fw))*255
__device__ float g_maskbw[NPIX];

struct Bilin {
    int i00, i01, i10, i11;
    float w00, w01, w10, w11;
};

__device__ __forceinline__ Bilin make_bilin(float fx, float fy, int x, int y) {
    float gx = fminf(fmaxf(fx + (float)x, 0.0f), (float)(W - 1));
    float gy = fminf(fmaxf(fy + (float)y, 0.0f), (float)(H - 1));
    float x0 = floorf(gx), y0 = floorf(gy);
    float wx = gx - x0, wy = gy - y0;
    int x0i = (int)x0, y0i = (int)y0;
    int x1i = min(x0i + 1, W - 1);
    int y1i = min(y0i + 1, H - 1);
    Bilin b;
    b.i00 = y0i * W + x0i;
    b.i01 = y0i * W + x1i;
    b.i10 = y1i * W + x0i;
    b.i11 = y1i * W + x1i;
    float ix = 1.0f - wx, iy = 1.0f - wy;
    b.w00 = ix * iy; b.w01 = wx * iy; b.w10 = ix * wy; b.w11 = wx * wy;
    return b;
}

__device__ __forceinline__ float samp(const float* __restrict__ p, const Bilin& bl) {
    return bl.w00 * __ldg(p + bl.i00) + bl.w01 * __ldg(p + bl.i01)
         + bl.w10 * __ldg(p + bl.i10) + bl.w11 * __ldg(p + bl.i11);
}

__device__ __forceinline__ float warp_reduce(float v) {
    #pragma unroll
    for (int o = 16; o > 0; o >>= 1) v += __shfl_down_sync(0xFFFFFFFFu, v, o);
    return v;
}

// FMA-pipe reciprocal: bit-hack seed + 2 Newton iterations.
// For x in (0.1, 5.1] rel err ~1e-6. Keeps the MUFU pipe free.
__device__ __forceinline__ float rcp_fma(float x) {
    float r = __uint_as_float(0x7EF477D5u - __float_as_uint(x));
    r = r * (2.0f - x * r);
    r = r * (2.0f - x * r);
    return r;
}

// Per-pixel: occ fw/bw, photometric loss partials, gray maps (round-7 form —
// k_main is L1-wavefront-bound at ~68us; confirmed closed)
__global__ void __launch_bounds__(256) k_main(const float* __restrict__ img1,
                                              const float* __restrict__ img2,
                                              const float* __restrict__ ffw,
                                              const float* __restrict__ fbw,
                                              float* __restrict__ out) {
    int i = blockIdx.x * blockDim.x + threadIdx.x;   // grid sized exactly
    int b = i / HW;
    int r = i - b * HW;
    int y = r / W;
    int x = r - y * W;

    const float* f1 = ffw + (size_t)b * 2 * HW;
    const float* f2 = fbw + (size_t)b * 2 * HW;
    float fwx = f1[r],       fwy = f1[HW + r];
    float bwx = f2[r],       bwy = f2[HW + r];

    Bilin bf = make_bilin(fwx, fwy, x, y);
    Bilin bb = make_bilin(bwx, bwy, x, y);

    // occ_fw = compute_occ(flow_fw, flow_bw)
    float bwwx = samp(f2, bf);
    float bwwy = samp(f2 + HW, bf);
    float dx0 = fwx + bwwx, dy0 = fwy + bwwy;
    float mag = dx0 * dx0 + dy0 * dy0;
    float fm  = fwx * fwx + fwy * fwy + bwwx * bwwx + bwwy * bwwy;
    float occf = (mag > fmaf(0.01f, fm, 0.5f)) ? 1.0f : 0.0f;
    out[3 + i] = occf;
    float mfw = 1.0f - occf;

    // occ_bw = compute_occ(flow_bw, flow_fw)
    float fwwx = samp(f1, bb);
    float fwwy = samp(f1 + HW, bb);
    float dx1 = bwx + fwwx, dy1 = bwy + fwwy;
    float mag1 = dx1 * dx1 + dy1 * dy1;
    float fm1  = bwx * bwx + bwy * bwy + fwwx * fwwx + fwwy * fwwy;
    float occb = (mag1 > fmaf(0.01f, fm1, 0.5f)) ? 1.0f : 0.0f;
    float mbw = 1.0f - occb;
    g_maskbw[i] = mbw;

    // image warps + photometric
    const float* i1 = img1 + (size_t)b * 3 * HW;
    const float* i2 = img2 + (size_t)b * 3 * HW;

    float w0 = samp(i2, bf), w1 = samp(i2 + HW, bf), w2 = samp(i2 + 2 * HW, bf);
    float a0 = i1[r], a1 = i1[HW + r], a2 = i1[2 * HW + r];
    float pfw = mfw * (__powf(fabsf(a0 - w0) + 0.01f, 0.4f)
                     + __powf(fabsf(a1 - w1) + 0.01f, 0.4f)
                     + __powf(fabsf(a2 - w2) + 0.01f, 0.4f));
    g_g2w[i] = (0.2989f * w0 + 0.587f * w1 + 0.114f * w2) * 255.0f;
    g_g1[i]  = (0.2989f * a0 + 0.587f * a1 + 0.114f * a2) * 255.0f;

    float v0 = samp(i1, bb), v1 = samp(i1 + HW, bb), v2 = samp(i1 + 2 * HW, bb);
    float c0 = i2[r], c1 = i2[HW + r], c2 = i2[2 * HW + r];
    float pbw = mbw * (__powf(fabsf(c0 - v0) + 0.01f, 0.4f)
                     + __powf(fabsf(c1 - v1) + 0.01f, 0.4f)
                     + __powf(fabsf(c2 - v2) + 0.01f, 0.4f));
    g_g1w[i] = (0.2989f * v0 + 0.587f * v1 + 0.114f * v2) * 255.0f;
    g_g2[i]  = (0.2989f * c0 + 0.587f * c1 + 0.114f * c2) * 255.0f;

    // block reduction: pfw, pbw, mfw, mbw
    float vals[4] = {pfw, pbw, mfw, mbw};
    __shared__ float red[8][4];
    int lane = threadIdx.x & 31, wid = threadIdx.x >> 5;
    #pragma unroll
    for (int k = 0; k < 4; k++) {
        float s = warp_reduce(vals[k]);
        if (lane == 0) red[wid][k] = s;
    }
    __syncthreads();
    if (threadIdx.x == 0) {
        float s0 = 0, s1 = 0, s2 = 0, s3 = 0;
        #pragma unroll
        for (int w = 0; w < 8; w++) { s0 += red[w][0]; s1 += red[w][1]; s2 += red[w][2]; s3 += red[w][3]; }
        atomicAdd(&g_acc[0], (double)s0);
        atomicAdd(&g_acc[1], (double)s1);
        atomicAdd(&g_acc[4], (double)s2);
        atomicAdd(&g_acc[5], (double)s3);
    }
}

// ---------------------------------------------------------------------------
// Census: 2 vertically-adjacent pixels per thread, 256 threads (32x8 thread
// shape, 32x16 pixel tile). Tap-row footprints of the two pixels overlap 6 of
// 8 rows: one loaded value serves tap dy=r of pixel0 and dy=r-1 of pixel1
// from a REGISTER (no exchange). Tile merged into one float4 array ->
// 1 LDS.128 per value instead of 2 LDS.64. Math per tap identical to the
// round-7 winner (Newton on (dy*7+dx)%3==0 taps). Last-block finalize kept.
// ---------------------------------------------------------------------------
constexpr int TX = 32, TY = 16;                  // pixel tile
constexpr int SW = TX + 6, SH = TY + 6;          // 38 x 22 value tile
constexpr int NCBLK = (W / TX) * (H / TY) * B;   // 4608 census blocks

// one tap-pair computation: value v vs center c, components:
//   (x,y) = fw pair (g1, g2w), (z,w) = bw pair (g2, g1w)
template<bool NEWTON>
__device__ __forceinline__ void tap(const float4& v, const float4& c,
                                    float& dsf, float& dsb) {
    float d1 = v.x - c.x;
    float t1 = d1 * rsqrtf(fmaf(d1, d1, 0.81f));
    float d2 = v.y - c.y;
    float t2 = d2 * rsqrtf(fmaf(d2, d2, 0.81f));
    float df = t1 - t2;
    float dd = df * df;
    if (NEWTON) dsf += dd * rcp_fma(0.1f + dd);
    else        dsf += __fdividef(dd, 0.1f + dd);

    float e1 = v.z - c.z;
    float u1 = e1 * rsqrtf(fmaf(e1, e1, 0.81f));
    float e2 = v.w - c.w;
    float u2 = e2 * rsqrtf(fmaf(e2, e2, 0.81f));
    float db = u1 - u2;
    float ee = db * db;
    if (NEWTON) dsb += ee * rcp_fma(0.1f + ee);
    else        dsb += __fdividef(ee, 0.1f + ee);
}

__global__ void __launch_bounds__(256) k_census(const float* __restrict__ occ_fw,
                                                float* __restrict__ out) {
    __shared__ float4 vt[SH][SW];   // (g1, g2w, g2, g1w)
    __shared__ float2 red[8];
    __shared__ bool is_last;

    int b   = blockIdx.z;
    int bx0 = blockIdx.x * TX;
    int by0 = blockIdx.y * TY;
    const float* p1  = g_g1  + (size_t)b * HW;
    const float* p2w = g_g2w + (size_t)b * HW;
    const float* p2  = g_g2  + (size_t)b * HW;
    const float* p1w = g_g1w + (size_t)b * HW;

    int tx = threadIdx.x, ty = threadIdx.y;   // 32 x 8 threads
    int tid = ty * TX + tx;

    for (int t = tid; t < SH * SW; t += 256) {
        int ly = t / SW, lx = t - ly * SW;
        int gy = by0 + ly - 3, gx = bx0 + lx - 3;
        float a = 0, bb = 0, c = 0, d = 0;
        if (gy >= 0 && gy < H && gx >= 0 && gx < W) {
            int gi = gy * W + gx;
            a = p1[gi]; bb = p2w[gi]; c = p2[gi]; d = p1w[gi];
        }
        vt[ly][lx] = make_float4(a, bb, c, d);
    }
    __syncthreads();

    // pixel0 tile row = 2*ty, pixel1 = 2*ty+1; padded center rows 2ty+3, 2ty+4
    float4 c0 = vt[2 * ty + 3][tx + 3];
    float4 c1 = vt[2 * ty + 4][tx + 3];

    float dsf0 = 0.0f, dsb0 = 0.0f, dsf1 = 0.0f, dsb1 = 0.0f;

    #pragma unroll
    for (int r = 0; r < 8; r++) {           // padded value row = 2ty + r
        #pragma unroll
        for (int dx = 0; dx < 7; dx++) {
            float4 v = vt[2 * ty + r][tx + dx];
            // pixel0: tap dy = r (valid r<=6), skip center (3,3)
            if (r <= 6 && !(r == 3 && dx == 3)) {
                if (((r * 7 + dx) % 3) == 0) tap<true >(v, c0, dsf0, dsb0);
                else                         tap<false>(v, c0, dsf0, dsb0);
            }
            // pixel1: tap dy = r-1 (valid r>=1), skip center (r==4, dx==3)
            if (r >= 1 && !(r == 4 && dx == 3)) {
                if ((((r - 1) * 7 + dx) % 3) == 0) tap<true >(v, c1, dsf1, dsb1);
                else                               tap<false>(v, c1, dsf1, dsb1);
            }
        }
    }

    int gx = bx0 + tx;
    int gy0 = by0 + 2 * ty;
    int i0 = b * HW + gy0 * W + gx;
    int i1 = i0 + W;

    float cf0 = __powf(dsf0 + 0.01f, 0.4f) * (1.0f - occ_fw[i0]);
    float cb0 = __powf(dsb0 + 0.01f, 0.4f) * g_maskbw[i0];
    float cf1 = __powf(dsf1 + 0.01f, 0.4f) * (1.0f - occ_fw[i1]);
    float cb1 = __powf(dsb1 + 0.01f, 0.4f) * g_maskbw[i1];

    int lane = tid & 31, wid = tid >> 5;
    float sf = warp_reduce(cf0 + cf1);
    float sb = warp_reduce(cb0 + cb1);
    if (lane == 0) red[wid] = make_float2(sf, sb);
    __syncthreads();
    if (tid == 0) {
        float a = 0, c = 0;
        #pragma unroll
        for (int w = 0; w < 8; w++) { a += red[w].x; c += red[w].y; }
        atomicAdd(&g_acc[2], (double)a);
        atomicAdd(&g_acc[3], (double)c);
        __threadfence();
        unsigned int old = atomicAdd(&g_ctr, 1u);
        is_last = (old == NCBLK - 1);
    }
    __syncthreads();

    // Last block finalizes (all prior g_acc atomics fenced before counter).
    if (is_last && tid == 0) {
        __threadfence();
        double dfw = g_acc[4] * 2.0 + 1e-6;
        double dbw = g_acc[5] * 2.0 + 1e-6;
        double photo  = g_acc[0] / dfw + g_acc[1] / dbw;
        double census = g_acc[2] / dfw + g_acc[3] / dbw;
        out[0] = (float)(photo + census);
        out[1] = (float)photo;
        out[2] = (float)census;
        #pragma unroll
        for (int k = 0; k < 6; k++) g_acc[k] = 0.0;
        g_ctr = 0u;
    }
}

extern "C" void kernel_launch(void* const* d_in, const int* in_sizes, int n_in,
                              void* d_out, int out_size) {
    const float* img1 = (const float*)d_in[0];
    const float* img2 = (const float*)d_in[1];
    const float* ffw  = (const float*)d_in[2];
    const float* fbw  = (const float*)d_in[3];
    float* out = (float*)d_out;

    k_main<<<NPIX / 256, 256>>>(img1, img2, ffw, fbw, out);
    dim3 cg(W / TX, H / TY, B);
    dim3 cb(32, 8, 1);
    k_census<<<cg, cb>>>(out + 3, out);
}